// round 15
// baseline (speedup 1.0000x reference)
#include <cuda_runtime.h>

#define BB 2
#define LL 2048
#define HH 12
#define DD 64
#define NBH (BB * HH)          // 24
#define ROW_STRIDE (HH * DD)   // 768
#define NEWTON_ITERS 6

// ---------------- device scratch ----------------
__device__ float  Sbuf[(size_t)NBH * LL * LL];   // 402 MB scores
__device__ float4 QFbuf[1572864];
__device__ float4 KFbuf[1572864];
__device__ float4 VFbuf[1572864];

#define NQF 786432
#define NKF 1572864
#define NVF 1572864

__device__ __forceinline__ float frcp(float x) {
    float r; asm("rcp.approx.f32 %0, %1;" : "=f"(r) : "f"(x)); return r;
}
__device__ __forceinline__ unsigned f2tf32(float x) {
    unsigned u; asm("cvt.rna.tf32.f32 %0, %1;" : "=r"(u) : "f"(x)); return u;
}
__device__ __forceinline__ void mma8f(float4& d, float4 a, unsigned b0, unsigned b1) {
    asm volatile(
        "mma.sync.aligned.m16n8k8.row.col.f32.tf32.tf32.f32 "
        "{%0,%1,%2,%3}, {%4,%5,%6,%7}, {%8,%9}, {%0,%1,%2,%3};\n"
        : "+f"(d.x), "+f"(d.y), "+f"(d.z), "+f"(d.w)
        : "r"(__float_as_uint(a.x)), "r"(__float_as_uint(a.y)),
          "r"(__float_as_uint(a.z)), "r"(__float_as_uint(a.w)),
          "r"(b0), "r"(b1));
}

// ---------------- prepass: build fragment buffers ----------------
__global__ void __launch_bounds__(256)
prepass_kernel(const float* __restrict__ gq, const float* __restrict__ gk,
               const float* __restrict__ gv) {
    int idx = blockIdx.x * 256 + threadIdx.x;
    int sec, id;
    if (idx < NQF)            { sec = 0; id = idx; }
    else if (idx < NQF + NKF) { sec = 1; id = idx - NQF; }
    else                      { sec = 2; id = idx - NQF - NKF; }
    int lane = id & 31;
    int g = lane >> 2, r = lane & 3;

    if (sec == 0) {
        int ks  = (id >> 5) & 7;
        int blk = (id >> 8) & 127;
        int bh  = id >> 15;
        int b = bh / HH, h = bh - b * HH;
        const size_t base = (size_t)b * LL * ROW_STRIDE + (size_t)h * DD;
        const float* p = gq + base + (size_t)(blk * 16 + g) * ROW_STRIDE + ks * 8 + r;
        float a0 = p[0] * 0.125f;
        float a1 = p[8 * ROW_STRIDE] * 0.125f;
        float a2 = p[4] * 0.125f;
        float a3 = p[8 * ROW_STRIDE + 4] * 0.125f;
        float4 hi, lo;
        hi.x = __uint_as_float(f2tf32(a0)); lo.x = a0 - hi.x;
        hi.y = __uint_as_float(f2tf32(a1)); lo.y = a1 - hi.y;
        hi.z = __uint_as_float(f2tf32(a2)); lo.z = a2 - hi.z;
        hi.w = __uint_as_float(f2tf32(a3)); lo.w = a3 - hi.w;
        QFbuf[(size_t)id * 2]     = hi;
        QFbuf[(size_t)id * 2 + 1] = lo;
    } else {
        int blk2 = (id >> 5) & 7;
        int blk  = (id >> 8) & 255;
        int bh   = id >> 16;
        int b = bh / HH, h = bh - b * HH;
        const size_t base = (size_t)b * LL * ROW_STRIDE + (size_t)h * DD;
        float x0, x1;
        if (sec == 1) {
            const float* p = gk + base + (size_t)(blk * 8 + g) * ROW_STRIDE + blk2 * 8 + r;
            x0 = p[0]; x1 = p[4];
        } else {
            const float* p = gv + base + (size_t)(blk * 8 + r) * ROW_STRIDE + blk2 * 8 + g;
            x0 = p[0]; x1 = p[4 * ROW_STRIDE];
        }
        float4 o;
        o.x = __uint_as_float(f2tf32(x0)); o.y = x0 - o.x;
        o.z = __uint_as_float(f2tf32(x1)); o.w = x1 - o.z;
        (sec == 1 ? KFbuf : VFbuf)[id] = o;
    }
}

// ---------------- kernel A: S = Q K^T (128q x 64k tile, 3-term tf32, R8-proven) ----
extern __shared__ float4 smemA[];

__global__ void __launch_bounds__(256, 2)
qk_kernel() {
    float4* sQf = smemA;          // 4096 f4 (64KB)
    float4* sKf = smemA + 4096;   // 2048 f4 (32KB)
    const int t = threadIdx.x, lane = t & 31, warp = t >> 5;
    const int g = lane >> 2, r = lane & 3;
    const int kt = blockIdx.x, qt = blockIdx.y, bh = blockIdx.z;

    const float4* qsrc = QFbuf + (size_t)(bh * 128 + qt * 8) * 512;
    const float4* ksrc = KFbuf + (size_t)(bh * 256 + kt * 8) * 256;
    #pragma unroll
    for (int i = 0; i < 16; ++i) sQf[t + i * 256] = qsrc[t + i * 256];
    #pragma unroll
    for (int i = 0; i < 8; ++i)  sKf[t + i * 256] = ksrc[t + i * 256];
    __syncthreads();

    const int mw = warp >> 1, nw = warp & 1;
    float4 C[2][4];
    #pragma unroll
    for (int mb = 0; mb < 2; ++mb)
        #pragma unroll
        for (int nb = 0; nb < 4; ++nb) C[mb][nb] = make_float4(0.f, 0.f, 0.f, 0.f);

    #pragma unroll
    for (int ks = 0; ks < 8; ++ks) {
        float4 qh0 = sQf[(((2 * mw    ) * 8 + ks) * 32 + lane) * 2    ];
        float4 ql0 = sQf[(((2 * mw    ) * 8 + ks) * 32 + lane) * 2 + 1];
        float4 qh1 = sQf[(((2 * mw + 1) * 8 + ks) * 32 + lane) * 2    ];
        float4 ql1 = sQf[(((2 * mw + 1) * 8 + ks) * 32 + lane) * 2 + 1];
        #pragma unroll
        for (int nb = 0; nb < 4; ++nb) {
            float4 kf = sKf[((nw * 4 + nb) * 8 + ks) * 32 + lane];
            unsigned b0h = __float_as_uint(kf.x), b0l = __float_as_uint(kf.y);
            unsigned b1h = __float_as_uint(kf.z), b1l = __float_as_uint(kf.w);
            mma8f(C[0][nb], qh0, b0h, b1h);
            mma8f(C[0][nb], qh0, b0l, b1l);
            mma8f(C[0][nb], ql0, b0h, b1h);
            mma8f(C[1][nb], qh1, b0h, b1h);
            mma8f(C[1][nb], qh1, b0l, b1l);
            mma8f(C[1][nb], ql1, b0h, b1h);
        }
    }

    const int q0 = qt * 128, k0 = kt * 64;
    #pragma unroll
    for (int mb = 0; mb < 2; ++mb)
        #pragma unroll
        for (int nb = 0; nb < 4; ++nb) {
            int row = q0 + (2 * mw + mb) * 16 + g;
            int col = k0 + (nw * 4 + nb) * 8 + 2 * r;
            float* sp = Sbuf + ((size_t)bh * LL + row) * LL + col;
            *reinterpret_cast<float2*>(sp)          = make_float2(C[mb][nb].x, C[mb][nb].y);
            *reinterpret_cast<float2*>(sp + 8 * LL) = make_float2(C[mb][nb].z, C[mb][nb].w);
        }
}

// ---------------- kernel C: fused Newton + O = W V (2-term) ----------------
// Prologue: each of 4 warps runs exact 6-iter Newton on 16 rows -> sc[64].
// Then the R8-proven chunk loop (W inline from S,c).
#define CW_STRIDE 68
extern __shared__ float smemC[];

__global__ void __launch_bounds__(128, 4)
wv_kernel(float* __restrict__ gout) {
    float*  sW  = smemC;                                          // 64*68 floats
    float*  sc  = smemC + 64 * CW_STRIDE;                         // 64 floats
    float4* sVF = reinterpret_cast<float4*>(smemC + 64 * CW_STRIDE + 64); // 2048 f4

    const int t = threadIdx.x, lane = t & 31, warp = t >> 5;
    const int g = lane >> 2, r = lane & 3;
    const int qt = blockIdx.x, bh = blockIdx.y;
    const int b = bh / HH, h = bh - b * HH;
    const int mw = warp >> 1, nw = warp & 1;   // 2x2 warp grid of m32n32

    const float* sbase = Sbuf + ((size_t)bh * LL + qt * 64) * LL;

    // ---- Newton phase: warp w handles local rows [w*16, w*16+16) ----
    {
        for (int rr = 0; rr < 16; ++rr) {
            const int row = warp * 16 + rr;
            const float* srow = sbase + (size_t)row * LL;

            float4 v[16];
            #pragma unroll
            for (int s = 0; s < 16; ++s)
                v[s] = *reinterpret_cast<const float4*>(srow + s * 128 + lane * 4);

            float m = -3.402823466e38f;
            #pragma unroll
            for (int s = 0; s < 16; ++s)
                m = fmaxf(m, fmaxf(fmaxf(v[s].x, v[s].y), fmaxf(v[s].z, v[s].w)));
            #pragma unroll
            for (int o = 16; o; o >>= 1) m = fmaxf(m, __shfl_xor_sync(0xffffffffu, m, o));
            float c = -m - 1.0f;

            for (int it = 0; it < NEWTON_ITERS; ++it) {
                float S = 0.f, Sd = 0.f;
                #pragma unroll
                for (int s = 0; s < 16; ++s) {
                    float i0 = frcp(-v[s].x - c), i1 = frcp(-v[s].y - c);
                    float i2 = frcp(-v[s].z - c), i3 = frcp(-v[s].w - c);
                    float s0 = i0*i0, s1 = i1*i1, s2 = i2*i2, s3 = i3*i3;
                    S  += (s0 + s1) + (s2 + s3);
                    Sd += (s0*i0 + s1*i1) + (s2*i2 + s3*i3);
                }
                #pragma unroll
                for (int o = 16; o; o >>= 1) {
                    S  += __shfl_xor_sync(0xffffffffu, S,  o);
                    Sd += __shfl_xor_sync(0xffffffffu, Sd, o);
                }
                c = c - (S - 1.0f) / (2.0f * Sd + 1e-8f);
            }

            if (lane == 0) sc[row] = c;
        }
    }
    __syncthreads();

    // ---- chunk loop (R8-proven) ----
    float4 C[2][4];
    #pragma unroll
    for (int mt = 0; mt < 2; ++mt)
        #pragma unroll
        for (int nb = 0; nb < 4; ++nb) C[mt][nb] = make_float4(0.f, 0.f, 0.f, 0.f);

    for (int ch = 0; ch < 32; ++ch) {
        // stage W chunk: 64 rows x 64 cols, computed from S and c
        #pragma unroll
        for (int i = 0; i < 8; ++i) {
            int idx = t + i * 128;              // 0..1023 f4
            int row = idx >> 4, c4 = (idx & 15) * 4;
            float4 s4 = *reinterpret_cast<const float4*>(
                sbase + (size_t)row * LL + ch * 64 + c4);
            float cc = sc[row];
            float i0 = frcp(-s4.x - cc), i1 = frcp(-s4.y - cc);
            float i2 = frcp(-s4.z - cc), i3 = frcp(-s4.w - cc);
            float4 w4 = make_float4(i0*i0, i1*i1, i2*i2, i3*i3);
            *reinterpret_cast<float4*>(sW + row * CW_STRIDE + c4) = w4;
        }
        // stage V fragments for this 64-token chunk
        const float4* vs = VFbuf + (size_t)(bh * 256 + ch * 8) * 256;
        #pragma unroll
        for (int i = 0; i < 16; ++i) sVF[t + i * 128] = vs[t + i * 128];
        __syncthreads();

        #pragma unroll
        for (int kb = 0; kb < 8; ++kb) {
            float4 ah[2];
            #pragma unroll
            for (int mt = 0; mt < 2; ++mt) {
                const float* wp = sW + (mw * 32 + mt * 16 + g) * CW_STRIDE + kb * 8 + r;
                ah[mt].x = __uint_as_float(f2tf32(wp[0]));
                ah[mt].y = __uint_as_float(f2tf32(wp[8 * CW_STRIDE]));
                ah[mt].z = __uint_as_float(f2tf32(wp[4]));
                ah[mt].w = __uint_as_float(f2tf32(wp[8 * CW_STRIDE + 4]));
            }
            #pragma unroll
            for (int nb = 0; nb < 4; ++nb) {
                float4 vf = sVF[(kb * 8 + nw * 4 + nb) * 32 + lane];
                unsigned b0h = __float_as_uint(vf.x), b0l = __float_as_uint(vf.y);
                unsigned b1h = __float_as_uint(vf.z), b1l = __float_as_uint(vf.w);
                mma8f(C[0][nb], ah[0], b0h, b1h);
                mma8f(C[0][nb], ah[0], b0l, b1l);
                mma8f(C[1][nb], ah[1], b0h, b1h);
                mma8f(C[1][nb], ah[1], b0l, b1l);
            }
        }
        __syncthreads();
    }

    const size_t obase = (size_t)b * LL * ROW_STRIDE + (size_t)h * DD;
    #pragma unroll
    for (int mt = 0; mt < 2; ++mt)
        #pragma unroll
        for (int nb = 0; nb < 4; ++nb) {
            int row = qt * 64 + mw * 32 + mt * 16 + g;
            int d   = nw * 32 + nb * 8 + 2 * r;
            float* op = gout + obase + (size_t)row * ROW_STRIDE + d;
            *reinterpret_cast<float2*>(op)                  = make_float2(C[mt][nb].x, C[mt][nb].y);
            *reinterpret_cast<float2*>(op + 8 * ROW_STRIDE) = make_float2(C[mt][nb].z, C[mt][nb].w);
        }
}

// ---------------- launch ----------------
extern "C" void kernel_launch(void* const* d_in, const int* in_sizes, int n_in,
                              void* d_out, int out_size) {
    const float* q = (const float*)d_in[0];
    const float* k = (const float*)d_in[1];
    const float* v = (const float*)d_in[2];
    float* out = (float*)d_out;

    const int SMEM_A = 6144 * 16;                               // 96 KB
    const int SMEM_C = (64 * CW_STRIDE + 64) * 4 + 2048 * 16;   // ~49.5 KB
    cudaFuncSetAttribute(qk_kernel, cudaFuncAttributeMaxDynamicSharedMemorySize, SMEM_A);
    cudaFuncSetAttribute(wv_kernel, cudaFuncAttributeMaxDynamicSharedMemorySize, SMEM_C);

    prepass_kernel<<<(NQF + NKF + NVF) / 256, 256>>>(q, k, v);

    dim3 gridA(32, 16, NBH);
    qk_kernel<<<gridA, 256, SMEM_A>>>();

    dim3 gridC(32, NBH);
    wv_kernel<<<gridC, 128, SMEM_C>>>(out);
}

// round 16
// speedup vs baseline: 1.0175x; 1.0175x over previous
#include <cuda_runtime.h>

#define BB 2
#define LL 2048
#define HH 12
#define DD 64
#define NBH (BB * HH)          // 24
#define ROW_STRIDE (HH * DD)   // 768
#define NEWTON_ITERS 6

// ---------------- device scratch ----------------
__device__ float  Sbuf[(size_t)NBH * LL * LL];   // 402 MB scores
__device__ float  Cbuf[NBH * LL];                // per-row Newton constant
__device__ float4 QFbuf[1572864];
__device__ float4 KFbuf[1572864];
__device__ float4 VFbuf[1572864];

#define NQF 786432
#define NKF 1572864
#define NVF 1572864

__device__ __forceinline__ float frcp(float x) {
    float r; asm("rcp.approx.f32 %0, %1;" : "=f"(r) : "f"(x)); return r;
}
__device__ __forceinline__ unsigned f2tf32(float x) {
    unsigned u; asm("cvt.rna.tf32.f32 %0, %1;" : "=r"(u) : "f"(x)); return u;
}
__device__ __forceinline__ void mma8f(float4& d, float4 a, unsigned b0, unsigned b1) {
    asm volatile(
        "mma.sync.aligned.m16n8k8.row.col.f32.tf32.tf32.f32 "
        "{%0,%1,%2,%3}, {%4,%5,%6,%7}, {%8,%9}, {%0,%1,%2,%3};\n"
        : "+f"(d.x), "+f"(d.y), "+f"(d.z), "+f"(d.w)
        : "r"(__float_as_uint(a.x)), "r"(__float_as_uint(a.y)),
          "r"(__float_as_uint(a.z)), "r"(__float_as_uint(a.w)),
          "r"(b0), "r"(b1));
}
__device__ __forceinline__ void cpasync16(void* dst_smem, const void* src) {
    unsigned d = (unsigned)__cvta_generic_to_shared(dst_smem);
    asm volatile("cp.async.ca.shared.global [%0], [%1], 16;\n" :: "r"(d), "l"(src));
}

// ---------------- prepass: build fragment buffers ----------------
__global__ void __launch_bounds__(256)
prepass_kernel(const float* __restrict__ gq, const float* __restrict__ gk,
               const float* __restrict__ gv) {
    int idx = blockIdx.x * 256 + threadIdx.x;
    int sec, id;
    if (idx < NQF)            { sec = 0; id = idx; }
    else if (idx < NQF + NKF) { sec = 1; id = idx - NQF; }
    else                      { sec = 2; id = idx - NQF - NKF; }
    int lane = id & 31;
    int g = lane >> 2, r = lane & 3;

    if (sec == 0) {
        int ks  = (id >> 5) & 7;
        int blk = (id >> 8) & 127;
        int bh  = id >> 15;
        int b = bh / HH, h = bh - b * HH;
        const size_t base = (size_t)b * LL * ROW_STRIDE + (size_t)h * DD;
        const float* p = gq + base + (size_t)(blk * 16 + g) * ROW_STRIDE + ks * 8 + r;
        float a0 = p[0] * 0.125f;
        float a1 = p[8 * ROW_STRIDE] * 0.125f;
        float a2 = p[4] * 0.125f;
        float a3 = p[8 * ROW_STRIDE + 4] * 0.125f;
        float4 hi, lo;
        hi.x = __uint_as_float(f2tf32(a0)); lo.x = a0 - hi.x;
        hi.y = __uint_as_float(f2tf32(a1)); lo.y = a1 - hi.y;
        hi.z = __uint_as_float(f2tf32(a2)); lo.z = a2 - hi.z;
        hi.w = __uint_as_float(f2tf32(a3)); lo.w = a3 - hi.w;
        QFbuf[(size_t)id * 2]     = hi;
        QFbuf[(size_t)id * 2 + 1] = lo;
    } else {
        int blk2 = (id >> 5) & 7;
        int blk  = (id >> 8) & 255;
        int bh   = id >> 16;
        int b = bh / HH, h = bh - b * HH;
        const size_t base = (size_t)b * LL * ROW_STRIDE + (size_t)h * DD;
        float x0, x1;
        if (sec == 1) {
            const float* p = gk + base + (size_t)(blk * 8 + g) * ROW_STRIDE + blk2 * 8 + r;
            x0 = p[0]; x1 = p[4];
        } else {
            const float* p = gv + base + (size_t)(blk * 8 + r) * ROW_STRIDE + blk2 * 8 + g;
            x0 = p[0]; x1 = p[4 * ROW_STRIDE];
        }
        float4 o;
        o.x = __uint_as_float(f2tf32(x0)); o.y = x0 - o.x;
        o.z = __uint_as_float(f2tf32(x1)); o.w = x1 - o.z;
        (sec == 1 ? KFbuf : VFbuf)[id] = o;
    }
}

// ---------------- kernel A: S = Q K^T, mega-tile 128q x 2048k, cp.async x2 ----------
// 512 threads (16 warps, 4m x 4n of m32n32). Q hoisted (64KB), K chunks of 128
// tokens (64KB) double-buffered. smem total 192KB, 1 CTA/SM, 384 CTAs.
#define QK_CH 16
extern __shared__ float4 smemA[];

__global__ void __launch_bounds__(512, 1)
qk_kernel() {
    float4* sQf = smemA;                              // 4096 f4
    float4* sKb[2] = { smemA + 4096, smemA + 8192 };  // 4096 f4 each

    const int t = threadIdx.x, lane = t & 31, warp = t >> 5;
    const int g = lane >> 2, r = lane & 3;
    const int qt = blockIdx.x, bh = blockIdx.y;
    const int mw = warp >> 2, nw = warp & 3;          // 4m x 4n

    const float4* qsrc = QFbuf + (size_t)(bh * 128 + qt * 8) * 512;
    const float4* ksrc = KFbuf + (size_t)bh * 65536;  // 65536 f4 per bh

    // prologue: G0 = {Q, K0}, G1 = {K1}
    #pragma unroll
    for (int i = 0; i < 8; ++i)
        cpasync16(sQf + t + i * 512, qsrc + t + i * 512);
    #pragma unroll
    for (int i = 0; i < 8; ++i)
        cpasync16(sKb[0] + t + i * 512, ksrc + t + i * 512);
    asm volatile("cp.async.commit_group;\n");
    #pragma unroll
    for (int i = 0; i < 8; ++i)
        cpasync16(sKb[1] + t + i * 512, ksrc + 4096 + t + i * 512);
    asm volatile("cp.async.commit_group;\n");

    const int q0 = qt * 128;

    #pragma unroll 1
    for (int c = 0; c < QK_CH; ++c) {
        if (c < QK_CH - 1) asm volatile("cp.async.wait_group 1;\n");
        else               asm volatile("cp.async.wait_group 0;\n");
        __syncthreads();

        const float4* sKf = sKb[c & 1];

        float4 C[2][4];
        #pragma unroll
        for (int mb = 0; mb < 2; ++mb)
            #pragma unroll
            for (int nb = 0; nb < 4; ++nb) C[mb][nb] = make_float4(0.f, 0.f, 0.f, 0.f);

        #pragma unroll
        for (int ks = 0; ks < 8; ++ks) {
            float4 qh0 = sQf[(((2 * mw    ) * 8 + ks) * 32 + lane) * 2    ];
            float4 ql0 = sQf[(((2 * mw    ) * 8 + ks) * 32 + lane) * 2 + 1];
            float4 qh1 = sQf[(((2 * mw + 1) * 8 + ks) * 32 + lane) * 2    ];
            float4 ql1 = sQf[(((2 * mw + 1) * 8 + ks) * 32 + lane) * 2 + 1];
            #pragma unroll
            for (int nb = 0; nb < 4; ++nb) {
                float4 kf = sKf[((nw * 4 + nb) * 8 + ks) * 32 + lane];
                unsigned b0h = __float_as_uint(kf.x), b0l = __float_as_uint(kf.y);
                unsigned b1h = __float_as_uint(kf.z), b1l = __float_as_uint(kf.w);
                mma8f(C[0][nb], qh0, b0h, b1h);
                mma8f(C[0][nb], qh0, b0l, b1l);
                mma8f(C[0][nb], ql0, b0h, b1h);
                mma8f(C[1][nb], qh1, b0h, b1h);
                mma8f(C[1][nb], qh1, b0l, b1l);
                mma8f(C[1][nb], ql1, b0h, b1h);
            }
        }

        const int k0 = c * 128;
        #pragma unroll
        for (int mb = 0; mb < 2; ++mb)
            #pragma unroll
            for (int nb = 0; nb < 4; ++nb) {
                int row = q0 + (2 * mw + mb) * 16 + g;
                int col = k0 + (nw * 4 + nb) * 8 + 2 * r;
                float* sp = Sbuf + ((size_t)bh * LL + row) * LL + col;
                *reinterpret_cast<float2*>(sp)          = make_float2(C[mb][nb].x, C[mb][nb].y);
                *reinterpret_cast<float2*>(sp + 8 * LL) = make_float2(C[mb][nb].z, C[mb][nb].w);
            }

        __syncthreads();   // buffer c&1 fully consumed before refill

        if (c + 2 < QK_CH) {
            const float4* src = ksrc + (size_t)(c + 2) * 4096;
            #pragma unroll
            for (int i = 0; i < 8; ++i)
                cpasync16(sKb[c & 1] + t + i * 512, src + t + i * 512);
            asm volatile("cp.async.commit_group;\n");
        }
    }
}

// ---------------- kernel B: Newton -> per-row constant c (exact, 6 iters) ----------------
__global__ void __launch_bounds__(256)
newton_kernel() {
    const int warp = threadIdx.x >> 5, lane = threadIdx.x & 31;
    const size_t rowid = (size_t)blockIdx.x * 8 + warp;
    const float* srow = Sbuf + rowid * LL;

    float4 v[16];
    #pragma unroll
    for (int s = 0; s < 16; ++s)
        v[s] = *reinterpret_cast<const float4*>(srow + s * 128 + lane * 4);

    float m = -3.402823466e38f;
    #pragma unroll
    for (int s = 0; s < 16; ++s)
        m = fmaxf(m, fmaxf(fmaxf(v[s].x, v[s].y), fmaxf(v[s].z, v[s].w)));
    #pragma unroll
    for (int o = 16; o; o >>= 1) m = fmaxf(m, __shfl_xor_sync(0xffffffffu, m, o));
    float c = -m - 1.0f;

    for (int it = 0; it < NEWTON_ITERS; ++it) {
        float S = 0.f, Sd = 0.f;
        #pragma unroll
        for (int s = 0; s < 16; ++s) {
            float i0 = frcp(-v[s].x - c), i1 = frcp(-v[s].y - c);
            float i2 = frcp(-v[s].z - c), i3 = frcp(-v[s].w - c);
            float s0 = i0*i0, s1 = i1*i1, s2 = i2*i2, s3 = i3*i3;
            S  += (s0 + s1) + (s2 + s3);
            Sd += (s0*i0 + s1*i1) + (s2*i2 + s3*i3);
        }
        #pragma unroll
        for (int o = 16; o; o >>= 1) {
            S  += __shfl_xor_sync(0xffffffffu, S,  o);
            Sd += __shfl_xor_sync(0xffffffffu, Sd, o);
        }
        c = c - (S - 1.0f) / (2.0f * Sd + 1e-8f);
    }

    if (lane == 0) Cbuf[rowid] = c;
}

// ---------------- kernel C: O = W V (2-term), W pre-converted to tf32 in staging ----
#define CW_STRIDE 68
extern __shared__ float smemC[];

__global__ void __launch_bounds__(128, 4)
wv_kernel(float* __restrict__ gout) {
    float*  sW  = smemC;                                          // 64*68 floats (tf32 bits)
    float*  sc  = smemC + 64 * CW_STRIDE;                         // 64 floats
    float4* sVF = reinterpret_cast<float4*>(smemC + 64 * CW_STRIDE + 64); // 2048 f4

    const int t = threadIdx.x, lane = t & 31, warp = t >> 5;
    const int g = lane >> 2, r = lane & 3;
    const int qt = blockIdx.x, bh = blockIdx.y;
    const int b = bh / HH, h = bh - b * HH;
    const int mw = warp >> 1, nw = warp & 1;   // 2x2 warp grid of m32n32

    if (t < 64) sc[t] = Cbuf[bh * LL + qt * 64 + t];

    float4 C[2][4];
    #pragma unroll
    for (int mt = 0; mt < 2; ++mt)
        #pragma unroll
        for (int nb = 0; nb < 4; ++nb) C[mt][nb] = make_float4(0.f, 0.f, 0.f, 0.f);

    const float* sbase = Sbuf + ((size_t)bh * LL + qt * 64) * LL;
    __syncthreads();

    for (int ch = 0; ch < 32; ++ch) {
        // stage W chunk: W = tf32(frcp(-s-c)^2), computed+converted ONCE per element
        #pragma unroll
        for (int i = 0; i < 8; ++i) {
            int idx = t + i * 128;              // 0..1023 f4
            int row = idx >> 4, c4 = (idx & 15) * 4;
            float4 s4 = *reinterpret_cast<const float4*>(
                sbase + (size_t)row * LL + ch * 64 + c4);
            float cc = sc[row];
            float i0 = frcp(-s4.x - cc), i1 = frcp(-s4.y - cc);
            float i2 = frcp(-s4.z - cc), i3 = frcp(-s4.w - cc);
            float4 w4;
            w4.x = __uint_as_float(f2tf32(i0 * i0));
            w4.y = __uint_as_float(f2tf32(i1 * i1));
            w4.z = __uint_as_float(f2tf32(i2 * i2));
            w4.w = __uint_as_float(f2tf32(i3 * i3));
            *reinterpret_cast<float4*>(sW + row * CW_STRIDE + c4) = w4;
        }
        // stage V fragments for this 64-token chunk
        const float4* vs = VFbuf + (size_t)(bh * 256 + ch * 8) * 256;
        #pragma unroll
        for (int i = 0; i < 16; ++i) sVF[t + i * 128] = vs[t + i * 128];
        __syncthreads();

        #pragma unroll
        for (int kb = 0; kb < 8; ++kb) {
            float4 ah[2];
            #pragma unroll
            for (int mt = 0; mt < 2; ++mt) {
                const float* wp = sW + (mw * 32 + mt * 16 + g) * CW_STRIDE + kb * 8 + r;
                ah[mt].x = wp[0];
                ah[mt].y = wp[8 * CW_STRIDE];
                ah[mt].z = wp[4];
                ah[mt].w = wp[8 * CW_STRIDE + 4];
            }
            #pragma unroll
            for (int nb = 0; nb < 4; ++nb) {
                float4 vf = sVF[(kb * 8 + nw * 4 + nb) * 32 + lane];
                unsigned b0h = __float_as_uint(vf.x), b0l = __float_as_uint(vf.y);
                unsigned b1h = __float_as_uint(vf.z), b1l = __float_as_uint(vf.w);
                mma8f(C[0][nb], ah[0], b0h, b1h);
                mma8f(C[0][nb], ah[0], b0l, b1l);
                mma8f(C[1][nb], ah[1], b0h, b1h);
                mma8f(C[1][nb], ah[1], b0l, b1l);
            }
        }
        __syncthreads();
    }

    const size_t obase = (size_t)b * LL * ROW_STRIDE + (size_t)h * DD;
    #pragma unroll
    for (int mt = 0; mt < 2; ++mt)
        #pragma unroll
        for (int nb = 0; nb < 4; ++nb) {
            int row = qt * 64 + mw * 32 + mt * 16 + g;
            int d   = nw * 32 + nb * 8 + 2 * r;
            float* op = gout + obase + (size_t)row * ROW_STRIDE + d;
            *reinterpret_cast<float2*>(op)                  = make_float2(C[mt][nb].x, C[mt][nb].y);
            *reinterpret_cast<float2*>(op + 8 * ROW_STRIDE) = make_float2(C[mt][nb].z, C[mt][nb].w);
        }
}

// ---------------- launch ----------------
extern "C" void kernel_launch(void* const* d_in, const int* in_sizes, int n_in,
                              void* d_out, int out_size) {
    const float* q = (const float*)d_in[0];
    const float* k = (const float*)d_in[1];
    const float* v = (const float*)d_in[2];
    float* out = (float*)d_out;

    const int SMEM_A = 12288 * 16;                              // 192 KB
    const int SMEM_C = (64 * CW_STRIDE + 64) * 4 + 2048 * 16;   // ~49.5 KB
    cudaFuncSetAttribute(qk_kernel, cudaFuncAttributeMaxDynamicSharedMemorySize, SMEM_A);
    cudaFuncSetAttribute(wv_kernel, cudaFuncAttributeMaxDynamicSharedMemorySize, SMEM_C);

    prepass_kernel<<<(NQF + NKF + NVF) / 256, 256>>>(q, k, v);

    dim3 gridA(16, NBH);               // 384 CTAs, 1/SM, Q hoisted, K pipelined
    qk_kernel<<<gridA, 512, SMEM_A>>>();

    newton_kernel<<<NBH * LL / 8, 256>>>();

    dim3 gridC(32, NBH);
    wv_kernel<<<gridC, 128, SMEM_C>>>(out);
}

// round 17
// speedup vs baseline: 1.0721x; 1.0537x over previous
#include <cuda_runtime.h>

#define BB 2
#define LL 2048
#define HH 12
#define DD 64
#define NBH (BB * HH)          // 24
#define ROW_STRIDE (HH * DD)   // 768
#define NEWTON_ITERS 6

// ---------------- device scratch ----------------
__device__ float  Sbuf[(size_t)NBH * LL * LL];   // 402 MB scores
__device__ float  Cbuf[NBH * LL];                // per-row Newton constant
__device__ float4 QFbuf[1572864];
__device__ float4 KFbuf[1572864];
__device__ float4 VFbuf[1572864];

#define NQF 786432
#define NKF 1572864
#define NVF 1572864

__device__ __forceinline__ float frcp(float x) {
    float r; asm("rcp.approx.f32 %0, %1;" : "=f"(r) : "f"(x)); return r;
}
__device__ __forceinline__ unsigned f2tf32(float x) {
    unsigned u; asm("cvt.rna.tf32.f32 %0, %1;" : "=r"(u) : "f"(x)); return u;
}
__device__ __forceinline__ void mma8f(float4& d, float4 a, unsigned b0, unsigned b1) {
    asm volatile(
        "mma.sync.aligned.m16n8k8.row.col.f32.tf32.tf32.f32 "
        "{%0,%1,%2,%3}, {%4,%5,%6,%7}, {%8,%9}, {%0,%1,%2,%3};\n"
        : "+f"(d.x), "+f"(d.y), "+f"(d.z), "+f"(d.w)
        : "r"(__float_as_uint(a.x)), "r"(__float_as_uint(a.y)),
          "r"(__float_as_uint(a.z)), "r"(__float_as_uint(a.w)),
          "r"(b0), "r"(b1));
}
__device__ __forceinline__ void cpasync16(void* dst_smem, const void* src) {
    unsigned d = (unsigned)__cvta_generic_to_shared(dst_smem);
    asm volatile("cp.async.ca.shared.global [%0], [%1], 16;\n" :: "r"(d), "l"(src));
}

// ---------------- prepass: build fragment buffers ----------------
__global__ void __launch_bounds__(256)
prepass_kernel(const float* __restrict__ gq, const float* __restrict__ gk,
               const float* __restrict__ gv) {
    int idx = blockIdx.x * 256 + threadIdx.x;
    int sec, id;
    if (idx < NQF)            { sec = 0; id = idx; }
    else if (idx < NQF + NKF) { sec = 1; id = idx - NQF; }
    else                      { sec = 2; id = idx - NQF - NKF; }
    int lane = id & 31;
    int g = lane >> 2, r = lane & 3;

    if (sec == 0) {
        int ks  = (id >> 5) & 7;
        int blk = (id >> 8) & 127;
        int bh  = id >> 15;
        int b = bh / HH, h = bh - b * HH;
        const size_t base = (size_t)b * LL * ROW_STRIDE + (size_t)h * DD;
        const float* p = gq + base + (size_t)(blk * 16 + g) * ROW_STRIDE + ks * 8 + r;
        float a0 = p[0] * 0.125f;
        float a1 = p[8 * ROW_STRIDE] * 0.125f;
        float a2 = p[4] * 0.125f;
        float a3 = p[8 * ROW_STRIDE + 4] * 0.125f;
        float4 hi, lo;
        hi.x = __uint_as_float(f2tf32(a0)); lo.x = a0 - hi.x;
        hi.y = __uint_as_float(f2tf32(a1)); lo.y = a1 - hi.y;
        hi.z = __uint_as_float(f2tf32(a2)); lo.z = a2 - hi.z;
        hi.w = __uint_as_float(f2tf32(a3)); lo.w = a3 - hi.w;
        QFbuf[(size_t)id * 2]     = hi;
        QFbuf[(size_t)id * 2 + 1] = lo;
    } else {
        int blk2 = (id >> 5) & 7;
        int blk  = (id >> 8) & 255;
        int bh   = id >> 16;
        int b = bh / HH, h = bh - b * HH;
        const size_t base = (size_t)b * LL * ROW_STRIDE + (size_t)h * DD;
        float x0, x1;
        if (sec == 1) {
            const float* p = gk + base + (size_t)(blk * 8 + g) * ROW_STRIDE + blk2 * 8 + r;
            x0 = p[0]; x1 = p[4];
        } else {
            const float* p = gv + base + (size_t)(blk * 8 + r) * ROW_STRIDE + blk2 * 8 + g;
            x0 = p[0]; x1 = p[4 * ROW_STRIDE];
        }
        float4 o;
        o.x = __uint_as_float(f2tf32(x0)); o.y = x0 - o.x;
        o.z = __uint_as_float(f2tf32(x1)); o.w = x1 - o.z;
        (sec == 1 ? KFbuf : VFbuf)[id] = o;
    }
}

// ---------------- kernel A: S = Q K^T (128q x 64k tile, 3-term tf32, cp.async load) ----
extern __shared__ float4 smemA[];

__global__ void __launch_bounds__(256, 2)
qk_kernel() {
    float4* sQf = smemA;          // 4096 f4 (64KB)
    float4* sKf = smemA + 4096;   // 2048 f4 (32KB)
    const int t = threadIdx.x, lane = t & 31, warp = t >> 5;
    const int g = lane >> 2, r = lane & 3;
    const int kt = blockIdx.x, qt = blockIdx.y, bh = blockIdx.z;

    const float4* qsrc = QFbuf + (size_t)(bh * 128 + qt * 8) * 512;
    const float4* ksrc = KFbuf + (size_t)(bh * 256 + kt * 8) * 256;
    #pragma unroll
    for (int i = 0; i < 16; ++i)
        cpasync16(sQf + t + i * 256, qsrc + t + i * 256);
    #pragma unroll
    for (int i = 0; i < 8; ++i)
        cpasync16(sKf + t + i * 256, ksrc + t + i * 256);
    asm volatile("cp.async.commit_group;\n");
    asm volatile("cp.async.wait_group 0;\n");
    __syncthreads();

    const int mw = warp >> 1, nw = warp & 1;
    float4 C[2][4];
    #pragma unroll
    for (int mb = 0; mb < 2; ++mb)
        #pragma unroll
        for (int nb = 0; nb < 4; ++nb) C[mb][nb] = make_float4(0.f, 0.f, 0.f, 0.f);

    #pragma unroll
    for (int ks = 0; ks < 8; ++ks) {
        float4 qh0 = sQf[(((2 * mw    ) * 8 + ks) * 32 + lane) * 2    ];
        float4 ql0 = sQf[(((2 * mw    ) * 8 + ks) * 32 + lane) * 2 + 1];
        float4 qh1 = sQf[(((2 * mw + 1) * 8 + ks) * 32 + lane) * 2    ];
        float4 ql1 = sQf[(((2 * mw + 1) * 8 + ks) * 32 + lane) * 2 + 1];
        #pragma unroll
        for (int nb = 0; nb < 4; ++nb) {
            float4 kf = sKf[((nw * 4 + nb) * 8 + ks) * 32 + lane];
            unsigned b0h = __float_as_uint(kf.x), b0l = __float_as_uint(kf.y);
            unsigned b1h = __float_as_uint(kf.z), b1l = __float_as_uint(kf.w);
            mma8f(C[0][nb], qh0, b0h, b1h);
            mma8f(C[0][nb], qh0, b0l, b1l);
            mma8f(C[0][nb], ql0, b0h, b1h);
            mma8f(C[1][nb], qh1, b0h, b1h);
            mma8f(C[1][nb], qh1, b0l, b1l);
            mma8f(C[1][nb], ql1, b0h, b1h);
        }
    }

    const int q0 = qt * 128, k0 = kt * 64;
    #pragma unroll
    for (int mb = 0; mb < 2; ++mb)
        #pragma unroll
        for (int nb = 0; nb < 4; ++nb) {
            int row = q0 + (2 * mw + mb) * 16 + g;
            int col = k0 + (nw * 4 + nb) * 8 + 2 * r;
            float* sp = Sbuf + ((size_t)bh * LL + row) * LL + col;
            *reinterpret_cast<float2*>(sp)          = make_float2(C[mb][nb].x, C[mb][nb].y);
            *reinterpret_cast<float2*>(sp + 8 * LL) = make_float2(C[mb][nb].z, C[mb][nb].w);
        }
}

// ---------------- kernel B: Newton -> per-row constant c (exact, 6 iters) ----------------
__global__ void __launch_bounds__(256)
newton_kernel() {
    const int warp = threadIdx.x >> 5, lane = threadIdx.x & 31;
    const size_t rowid = (size_t)blockIdx.x * 8 + warp;
    const float* srow = Sbuf + rowid * LL;

    float4 v[16];
    #pragma unroll
    for (int s = 0; s < 16; ++s)
        v[s] = *reinterpret_cast<const float4*>(srow + s * 128 + lane * 4);

    float m = -3.402823466e38f;
    #pragma unroll
    for (int s = 0; s < 16; ++s)
        m = fmaxf(m, fmaxf(fmaxf(v[s].x, v[s].y), fmaxf(v[s].z, v[s].w)));
    #pragma unroll
    for (int o = 16; o; o >>= 1) m = fmaxf(m, __shfl_xor_sync(0xffffffffu, m, o));
    float c = -m - 1.0f;

    for (int it = 0; it < NEWTON_ITERS; ++it) {
        float S = 0.f, Sd = 0.f;
        #pragma unroll
        for (int s = 0; s < 16; ++s) {
            float i0 = frcp(-v[s].x - c), i1 = frcp(-v[s].y - c);
            float i2 = frcp(-v[s].z - c), i3 = frcp(-v[s].w - c);
            float s0 = i0*i0, s1 = i1*i1, s2 = i2*i2, s3 = i3*i3;
            S  += (s0 + s1) + (s2 + s3);
            Sd += (s0*i0 + s1*i1) + (s2*i2 + s3*i3);
        }
        #pragma unroll
        for (int o = 16; o; o >>= 1) {
            S  += __shfl_xor_sync(0xffffffffu, S,  o);
            Sd += __shfl_xor_sync(0xffffffffu, Sd, o);
        }
        c = c - (S - 1.0f) / (2.0f * Sd + 1e-8f);
    }

    if (lane == 0) Cbuf[rowid] = c;
}

// ---------------- kernel C: O = W V (2-term), tf32 W staging, async V staging ----
#define CW_STRIDE 68
extern __shared__ float smemC[];

__global__ void __launch_bounds__(128, 4)
wv_kernel(float* __restrict__ gout) {
    float*  sW  = smemC;                                          // 64*68 floats (tf32 bits)
    float*  sc  = smemC + 64 * CW_STRIDE;                         // 64 floats
    float4* sVF = reinterpret_cast<float4*>(smemC + 64 * CW_STRIDE + 64); // 2048 f4

    const int t = threadIdx.x, lane = t & 31, warp = t >> 5;
    const int g = lane >> 2, r = lane & 3;
    const int qt = blockIdx.x, bh = blockIdx.y;
    const int b = bh / HH, h = bh - b * HH;
    const int mw = warp >> 1, nw = warp & 1;   // 2x2 warp grid of m32n32

    if (t < 64) sc[t] = Cbuf[bh * LL + qt * 64 + t];

    float4 C[2][4];
    #pragma unroll
    for (int mt = 0; mt < 2; ++mt)
        #pragma unroll
        for (int nb = 0; nb < 4; ++nb) C[mt][nb] = make_float4(0.f, 0.f, 0.f, 0.f);

    const float* sbase = Sbuf + ((size_t)bh * LL + qt * 64) * LL;
    __syncthreads();

    for (int ch = 0; ch < 32; ++ch) {
        // V staging first via cp.async (latency overlaps the W-compute below)
        const float4* vs = VFbuf + (size_t)(bh * 256 + ch * 8) * 256;
        #pragma unroll
        for (int i = 0; i < 16; ++i)
            cpasync16(sVF + t + i * 128, vs + t + i * 128);
        asm volatile("cp.async.commit_group;\n");

        // stage W chunk: W = tf32(frcp(-s-c)^2), computed+converted ONCE per element
        #pragma unroll
        for (int i = 0; i < 8; ++i) {
            int idx = t + i * 128;              // 0..1023 f4
            int row = idx >> 4, c4 = (idx & 15) * 4;
            float4 s4 = *reinterpret_cast<const float4*>(
                sbase + (size_t)row * LL + ch * 64 + c4);
            float cc = sc[row];
            float i0 = frcp(-s4.x - cc), i1 = frcp(-s4.y - cc);
            float i2 = frcp(-s4.z - cc), i3 = frcp(-s4.w - cc);
            float4 w4;
            w4.x = __uint_as_float(f2tf32(i0 * i0));
            w4.y = __uint_as_float(f2tf32(i1 * i1));
            w4.z = __uint_as_float(f2tf32(i2 * i2));
            w4.w = __uint_as_float(f2tf32(i3 * i3));
            *reinterpret_cast<float4*>(sW + row * CW_STRIDE + c4) = w4;
        }

        asm volatile("cp.async.wait_group 0;\n");
        __syncthreads();

        #pragma unroll
        for (int kb = 0; kb < 8; ++kb) {
            float4 ah[2];
            #pragma unroll
            for (int mt = 0; mt < 2; ++mt) {
                const float* wp = sW + (mw * 32 + mt * 16 + g) * CW_STRIDE + kb * 8 + r;
                ah[mt].x = wp[0];
                ah[mt].y = wp[8 * CW_STRIDE];
                ah[mt].z = wp[4];
                ah[mt].w = wp[8 * CW_STRIDE + 4];
            }
            #pragma unroll
            for (int nb = 0; nb < 4; ++nb) {
                float4 vf = sVF[(kb * 8 + nw * 4 + nb) * 32 + lane];
                unsigned b0h = __float_as_uint(vf.x), b0l = __float_as_uint(vf.y);
                unsigned b1h = __float_as_uint(vf.z), b1l = __float_as_uint(vf.w);
                mma8f(C[0][nb], ah[0], b0h, b1h);
                mma8f(C[0][nb], ah[0], b0l, b1l);
                mma8f(C[1][nb], ah[1], b0h, b1h);
                mma8f(C[1][nb], ah[1], b0l, b1l);
            }
        }
        __syncthreads();
    }

    const size_t obase = (size_t)b * LL * ROW_STRIDE + (size_t)h * DD;
    #pragma unroll
    for (int mt = 0; mt < 2; ++mt)
        #pragma unroll
        for (int nb = 0; nb < 4; ++nb) {
            int row = qt * 64 + mw * 32 + mt * 16 + g;
            int d   = nw * 32 + nb * 8 + 2 * r;
            float* op = gout + obase + (size_t)row * ROW_STRIDE + d;
            *reinterpret_cast<float2*>(op)                  = make_float2(C[mt][nb].x, C[mt][nb].y);
            *reinterpret_cast<float2*>(op + 8 * ROW_STRIDE) = make_float2(C[mt][nb].z, C[mt][nb].w);
        }
}

// ---------------- launch ----------------
extern "C" void kernel_launch(void* const* d_in, const int* in_sizes, int n_in,
                              void* d_out, int out_size) {
    const float* q = (const float*)d_in[0];
    const float* k = (const float*)d_in[1];
    const float* v = (const float*)d_in[2];
    float* out = (float*)d_out;

    const int SMEM_A = 6144 * 16;                               // 96 KB
    const int SMEM_C = (64 * CW_STRIDE + 64) * 4 + 2048 * 16;   // ~49.5 KB
    cudaFuncSetAttribute(qk_kernel, cudaFuncAttributeMaxDynamicSharedMemorySize, SMEM_A);
    cudaFuncSetAttribute(wv_kernel, cudaFuncAttributeMaxDynamicSharedMemorySize, SMEM_C);

    prepass_kernel<<<(NQF + NKF + NVF) / 256, 256>>>(q, k, v);

    dim3 gridA(32, 16, NBH);
    qk_kernel<<<gridA, 256, SMEM_A>>>();

    newton_kernel<<<NBH * LL / 8, 256>>>();

    dim3 gridC(32, NBH);
    wv_kernel<<<gridC, 128, SMEM_C>>>(out);
}